// round 11
// baseline (speedup 1.0000x reference)
#include <cuda_runtime.h>
#include <cstdint>

#define D 128

union V32 { unsigned long long u[4]; float f[8]; };

// 256-bit non-coherent load with L2::evict_last (only legal width on sm_103).
__device__ __forceinline__ V32 ldg256_el(const float* p)
{
    V32 v;
    asm volatile("ld.global.nc.L2::evict_last.v4.b64 {%0,%1,%2,%3}, [%4];"
                 : "=l"(v.u[0]), "=l"(v.u[1]), "=l"(v.u[2]), "=l"(v.u[3])
                 : "l"(p));
    return v;
}

struct Task { int i0, i1, i2, j0, j1, j2; };  // row0 / row1 triples

__device__ __forceinline__ Task load_task_idx(const int* __restrict__ x, int task)
{
    const int2* p = (const int2*)(x + (size_t)task * 6);
    int2 a = __ldg(p + 0), b = __ldg(p + 1), c = __ldg(p + 2);
    Task t;
    t.i0 = a.x; t.i1 = a.y; t.i2 = b.x;
    t.j0 = b.y; t.j1 = c.x; t.j2 = c.y;
    return t;
}

__device__ __forceinline__ void gather6(
    V32& tb, V32& ta, V32& tc, V32& cb, V32& ca, V32& cc,
    const Task& t, int half, int sub,
    const float* __restrict__ tgt_base, const float* __restrict__ tgt_a,
    const float* __restrict__ tgt_b,    const float* __restrict__ ctx_base,
    const float* __restrict__ ctx_a,    const float* __restrict__ ctx_b)
{
    const int i0 = half ? t.j0 : t.i0;
    const int i1 = half ? t.j1 : t.i1;
    const int i2 = half ? t.j2 : t.i2;
    const int off = sub * 8;
    tb = ldg256_el(tgt_base + (size_t)i0 * D + off);
    ta = ldg256_el(tgt_a    + (size_t)i1 * D + off);
    tc = ldg256_el(tgt_b    + (size_t)i2 * D + off);
    cb = ldg256_el(ctx_base + (size_t)i0 * D + off);
    ca = ldg256_el(ctx_a    + (size_t)i1 * D + off);
    cc = ldg256_el(ctx_b    + (size_t)i2 * D + off);
}

__device__ __forceinline__ float dot8(
    const V32& tb, const V32& ta, const V32& tc,
    const V32& cb, const V32& ca, const V32& cc,
    float w0, float w1, float w2, float v0, float v1, float v2)
{
    float p = 0.0f;
    #pragma unroll
    for (int j = 0; j < 8; j++) {
        float t = w0 * tb.f[j] + w1 * ta.f[j] + w2 * tc.f[j];
        float c = v0 * cb.f[j] + v1 * ca.f[j] + v2 * cc.f[j];
        p += t * c;
    }
    return p;
}

__device__ __forceinline__ void reduce_store(
    float p, int lane, int task, int bs, float* __restrict__ out)
{
    #pragma unroll
    for (int o = 8; o > 0; o >>= 1)
        p += __shfl_xor_sync(0xFFFFFFFFu, p, o);
    float q = __shfl_xor_sync(0xFFFFFFFFu, p, 16);
    if (lane == 0) {
        const int r0 = task * 2;
        float s0 = __frcp_rn(1.0f + __expf(-p));
        float s1 = __frcp_rn(1.0f + __expf(-q));
        if (r0 + 1 < bs) *(float2*)(out + r0) = make_float2(s0, s1);
        else             out[r0] = s0;
    }
}

// Exactly one resident wave (4096 warps); each warp runs 2 tasks, with task-2's
// gathers issued BEFORE task-1's shuffle epilogue so the epilogue hides latency.
__global__ __launch_bounds__(64) void sgns_kernel11(
    const int*   __restrict__ x,
    const float* __restrict__ tgt_base, const float* __restrict__ tgt_a,
    const float* __restrict__ tgt_b,    const float* __restrict__ ctx_base,
    const float* __restrict__ ctx_a,    const float* __restrict__ ctx_b,
    const float* __restrict__ tgt_w,    const float* __restrict__ ctx_w,
    float* __restrict__ out, int ntasks, int bs)
{
    const int warp = (blockIdx.x * blockDim.x + threadIdx.x) >> 5;
    const int lane = threadIdx.x & 31;
    const int half = lane >> 4;
    const int sub  = lane & 15;
    const int nw   = gridDim.x * 2;          // total warps
    const int t1   = warp;
    const int t2   = warp + nw;
    if (t1 >= ntasks) return;

    // indices for both tasks up front
    Task k1 = load_task_idx(x, t1);
    const bool has2 = (t2 < ntasks);
    Task k2 = has2 ? load_task_idx(x, t2) : k1;

    // task-1 gathers
    V32 tb, ta, tc, cb, ca, cc;
    gather6(tb, ta, tc, cb, ca, cc, k1, half, sub,
            tgt_base, tgt_a, tgt_b, ctx_base, ctx_a, ctx_b);

    // softmax weights (overlap with gather latency)
    float tw0 = __ldg(&tgt_w[0]), tw1 = __ldg(&tgt_w[1]), tw2 = __ldg(&tgt_w[2]);
    float tm  = fmaxf(tw0, fmaxf(tw1, tw2));
    float te0 = __expf(tw0 - tm), te1 = __expf(tw1 - tm), te2 = __expf(tw2 - tm);
    float ti  = __frcp_rn(te0 + te1 + te2);
    const float w0 = te0 * ti, w1 = te1 * ti, w2 = te2 * ti;

    float cw0 = __ldg(&ctx_w[0]), cw1 = __ldg(&ctx_w[1]), cw2 = __ldg(&ctx_w[2]);
    float cm  = fmaxf(cw0, fmaxf(cw1, cw2));
    float ce0 = __expf(cw0 - cm), ce1 = __expf(cw1 - cm), ce2 = __expf(cw2 - cm);
    float ci  = __frcp_rn(ce0 + ce1 + ce2);
    const float v0 = ce0 * ci, v1 = ce1 * ci, v2 = ce2 * ci;

    // task-1 per-lane dot (kills the 48 data regs)
    float p1 = dot8(tb, ta, tc, cb, ca, cc, w0, w1, w2, v0, v1, v2);

    if (has2) {
        // task-2 gathers issue NOW — task-1's epilogue hides their latency
        gather6(tb, ta, tc, cb, ca, cc, k2, half, sub,
                tgt_base, tgt_a, tgt_b, ctx_base, ctx_a, ctx_b);

        reduce_store(p1, lane, t1, bs, out);

        float p2 = dot8(tb, ta, tc, cb, ca, cc, w0, w1, w2, v0, v1, v2);
        reduce_store(p2, lane, t2, bs, out);
    } else {
        reduce_store(p1, lane, t1, bs, out);
    }
}

extern "C" void kernel_launch(void* const* d_in, const int* in_sizes, int n_in,
                              void* d_out, int out_size)
{
    const int*   x        = (const int*)  d_in[0];
    const float* tgt_base = (const float*)d_in[1];
    const float* tgt_a    = (const float*)d_in[2];
    const float* tgt_b    = (const float*)d_in[3];
    const float* ctx_base = (const float*)d_in[4];
    const float* ctx_a    = (const float*)d_in[5];
    const float* ctx_b    = (const float*)d_in[6];
    const float* tgt_w    = (const float*)d_in[7];
    const float* ctx_w    = (const float*)d_in[8];
    float* out = (float*)d_out;

    const int bs     = in_sizes[0] / 3;
    const int ntasks = (bs + 1) / 2;          // 2 batch rows per task

    // one resident wave: ceil(ntasks/2) warps, 2 warps per 64-thr block
    const int warps  = (ntasks + 1) / 2;
    const int blocks = (warps + 1) / 2;       // 2048 for BS=16384

    sgns_kernel11<<<blocks, 64>>>(x, tgt_base, tgt_a, tgt_b,
                                  ctx_base, ctx_a, ctx_b,
                                  tgt_w, ctx_w, out, ntasks, bs);
}